// round 7
// baseline (speedup 1.0000x reference)
#include <cuda_runtime.h>
#include <math.h>

#define NB 8
#define NH 1024
#define NW 1024
#define HW (1 << 20)
#define BHW (NB * HW)

#define NU 0.01f
#define DT 0.01f

#define C1ROW 520                      // compact spectral row stride (slots 0..512 used, natural kx)
#define C1BATCH (1024 * C1ROW)

// ------------------------- device scratch -------------------------
__device__ float  g_fa[2 * BHW];
__device__ float  g_unew[BHW];
__device__ float  g_vnew[BHW];
__device__ float2 g_c1[NB * C1BATCH];
__device__ float  g_pcorr[BHW];
__device__ float  g_partials[16384];
__device__ float  g_invnorm[16];

// ------------------------- complex helpers -------------------------
__device__ __forceinline__ float2 cmul(float2 a, float2 b) {
    return make_float2(a.x * b.x - a.y * b.y, a.x * b.y + a.y * b.x);
}
__device__ __forceinline__ float2 cadd(float2 a, float2 b) { return make_float2(a.x + b.x, a.y + b.y); }
__device__ __forceinline__ float2 csub(float2 a, float2 b) { return make_float2(a.x - b.x, a.y - b.y); }

__device__ __forceinline__ constexpr int brev5(int v) {
    return ((v & 1) << 4) | ((v & 2) << 2) | (v & 4) | ((v & 8) >> 2) | ((v & 16) >> 4);
}

// W_32^q = exp(-2*pi*i*q/32), q=0..15
__constant__ float2 W32C[16] = {
    { 1.000000000f, -0.000000000f}, { 0.980785280f, -0.195090322f},
    { 0.923879533f, -0.382683432f}, { 0.831469612f, -0.555570233f},
    { 0.707106781f, -0.707106781f}, { 0.555570233f, -0.831469612f},
    { 0.382683432f, -0.923879533f}, { 0.195090322f, -0.980785280f},
    { 0.000000000f, -1.000000000f}, {-0.195090322f, -0.980785280f},
    {-0.382683432f, -0.923879533f}, {-0.555570233f, -0.831469612f},
    {-0.707106781f, -0.707106781f}, {-0.831469612f, -0.555570233f},
    {-0.923879533f, -0.382683432f}, {-0.980785280f, -0.195090322f},
};

// 32-pt in-place DIF (natural in, X[k] at r[brev5(k)])
__device__ __forceinline__ void dif32(float2* r) {
    #pragma unroll
    for (int t = 0; t < 5; t++) {
        const int h = 16 >> t;
        #pragma unroll
        for (int g = 0; g < (16 / h); g++) {
            #pragma unroll
            for (int q = 0; q < h; q++) {
                int i0 = ((g * h) << 1) + q, i1 = i0 + h;
                float2 A = r[i0], B = r[i1];
                r[i0] = cadd(A, B);
                r[i1] = cmul(csub(A, B), W32C[q << t]);
            }
        }
    }
}

// 32-pt in-place inverse DIT with conj twiddles (input r[j]=X[brev5(j)], natural out, unscaled)
__device__ __forceinline__ void dit32i(float2* r) {
    #pragma unroll
    for (int t = 0; t < 5; t++) {
        const int h = 1 << t;
        #pragma unroll
        for (int g = 0; g < (16 / h); g++) {
            #pragma unroll
            for (int q = 0; q < h; q++) {
                int i0 = ((g * h) << 1) + q, i1 = i0 + h;
                float2 A = r[i0], B = r[i1];
                float2 w = W32C[q << (4 - t)];
                w.y = -w.y;
                float2 tv = cmul(w, B);
                r[i0] = cadd(A, tv);
                r[i1] = csub(A, tv);
            }
        }
    }
}

// Warp 1024-pt forward FFT. In: r[n1] = z[32*n1 + lane]. Out: r[j] = Z[32*brev5(j) + lane].
// zb: per-warp float2[1056] scratch (32x33).
__device__ __forceinline__ void fft1024_warp(float2* r, float2* zb, int lane) {
    dif32(r);
    float sn, cs;
    sincosf((float)lane * -6.135923151542565e-3f, &sn, &cs);   // -2*pi*lane/1024
    float2 w1 = make_float2(cs, sn), w = w1;
    #pragma unroll
    for (int k1 = 1; k1 < 32; k1++) {
        r[brev5(k1)] = cmul(r[brev5(k1)], w);
        w = cmul(w, w1);
    }
    __syncwarp();
    #pragma unroll
    for (int k1 = 0; k1 < 32; k1++) zb[lane * 33 + k1] = r[brev5(k1)];
    __syncwarp();
    #pragma unroll
    for (int n2 = 0; n2 < 32; n2++) r[n2] = zb[n2 * 33 + lane];
    dif32(r);
}

// Warp 1024-pt inverse FFT (unscaled). In: r[j] = X[32*brev5(j) + lane]. Out: r[n1] = x[32*n1 + lane].
__device__ __forceinline__ void ifft1024_warp(float2* r, float2* zb, int lane) {
    dit32i(r);
    float sn, cs;
    sincosf((float)lane * 6.135923151542565e-3f, &sn, &cs);    // +2*pi*lane/1024
    float2 w1 = make_float2(cs, sn), w = w1;
    #pragma unroll
    for (int n2 = 1; n2 < 32; n2++) {
        r[n2] = cmul(r[n2], w);
        w = cmul(w, w1);
    }
    __syncwarp();
    #pragma unroll
    for (int n2 = 0; n2 < 32; n2++) zb[lane * 33 + n2] = r[n2];
    __syncwarp();
    #pragma unroll
    for (int j = 0; j < 32; j++) r[j] = zb[brev5(j) * 33 + lane];
    dit32i(r);
}

// ------------------------- block reduce -------------------------
__device__ __forceinline__ float block_reduce_256(float v, float* red) {
    #pragma unroll
    for (int o = 16; o > 0; o >>= 1) v += __shfl_down_sync(0xffffffffu, v, o);
    int lane = threadIdx.x & 31, wid = threadIdx.x >> 5;
    if (lane == 0) red[wid] = v;
    __syncthreads();
    float s = 0.0f;
    if (wid == 0) {
        s = (lane < 8) ? red[lane] : 0.0f;
        #pragma unroll
        for (int o = 4; o > 0; o >>= 1) s += __shfl_down_sync(0xffffffffu, s, o);
    }
    return s;
}

// ------------------------- fused 3x smoothing + norm partials -------------------------
__global__ void smooth3_kernel(const float* __restrict__ su_ext,
                               const float* __restrict__ sv_ext) {
    __shared__ float t0[38][40];
    __shared__ float t1[38][40];
    __shared__ float red[8];
    int slab = blockIdx.y;
    int fb = slab >> 3, b = slab & 7;
    const float* src = (fb ? sv_ext : su_ext) + (b << 20);
    int tile = blockIdx.x;
    int ty0 = (tile >> 5) << 5;
    int tx0 = (tile & 31) << 5;
    int tid = threadIdx.x;

    for (int i = tid; i < 38 * 38; i += 256) {
        int ly = i / 38, lx = i - ly * 38;
        int gy = (ty0 + ly - 3) & 1023;
        int gx = (tx0 + lx - 3) & 1023;
        t0[ly][lx] = src[(gy << 10) + gx];
    }
    __syncthreads();
    for (int i = tid; i < 36 * 36; i += 256) {
        int ly = i / 36, lx = i - ly * 36;
        ly += 1; lx += 1;
        float c = t0[ly][lx];
        t1[ly][lx] = c + 0.1f * (t0[ly][lx-1] + t0[ly][lx+1] + t0[ly-1][lx] + t0[ly+1][lx] - 4.0f * c);
    }
    __syncthreads();
    for (int i = tid; i < 34 * 34; i += 256) {
        int ly = i / 34, lx = i - ly * 34;
        ly += 2; lx += 2;
        float c = t1[ly][lx];
        t0[ly][lx] = c + 0.1f * (t1[ly][lx-1] + t1[ly][lx+1] + t1[ly-1][lx] + t1[ly+1][lx] - 4.0f * c);
    }
    __syncthreads();
    float ss = 0.0f;
    float* dst = g_fa + fb * BHW + (b << 20);
    for (int i = tid; i < 1024; i += 256) {
        int ly = (i >> 5) + 3, lx = (i & 31) + 3;
        float c = t0[ly][lx];
        float o = c + 0.1f * (t0[ly][lx-1] + t0[ly][lx+1] + t0[ly-1][lx] + t0[ly+1][lx] - 4.0f * c);
        dst[((ty0 + ly - 3) << 10) + (tx0 + lx - 3)] = o;
        ss += o * o;
    }
    float tot = block_reduce_256(ss, red);
    if (tid == 0) g_partials[slab * 1024 + tile] = tot;
}

__global__ void finalize_kernel() {
    int r = blockIdx.x;
    float s = 0.0f;
    for (int i = threadIdx.x; i < 1024; i += 256) s += g_partials[r * 1024 + i];
    __shared__ float red[8];
    float tot = block_reduce_256(s, red);
    if (threadIdx.x == 0) {
        float nrm = sqrtf(tot);
        g_invnorm[r] = 1.0f / fmaxf(nrm, 1e-12f);
    }
}

// ------------------------- main update -------------------------
__global__ void update_kernel(const float* __restrict__ xin,
                              const float* __restrict__ beta) {
    int gid = blockIdx.x * 256 + threadIdx.x;
    int b  = gid >> 20;
    int yx = gid & (HW - 1);
    int y = yx >> 10, x = yx & 1023;

    const float* u = xin + (size_t)(b * 3 + 0) * HW;
    const float* v = xin + (size_t)(b * 3 + 1) * HW;
    const float* p = xin + (size_t)(b * 3 + 2) * HW;

    int ixp = (y << 10) | ((x + 1) & 1023);
    int ixm = (y << 10) | ((x - 1) & 1023);
    int iyp = (((y + 1) & 1023) << 10) | x;
    int iym = (((y - 1) & 1023) << 10) | x;

    float uc = u[yx], uxp = u[ixp], uxm = u[ixm], uyp = u[iyp], uym = u[iym];
    float vc = v[yx], vxp = v[ixp], vxm = v[ixm], vyp = v[iyp], vym = v[iym];
    float pxp = p[ixp], pxm = p[ixm], pyp = p[iyp], pym = p[iym];

    float adv_u = uc * 0.5f * (uxp - uxm) + vc * 0.5f * (uyp - uym);
    float adv_v = uc * 0.5f * (vxp - vxm) + vc * 0.5f * (vyp - vym);
    float lap_u = uxp + uxm + uyp + uym - 4.0f * uc;
    float lap_v = vxp + vxm + vyp + vym - 4.0f * vc;
    float dpdx = 0.5f * (pxp - pxm), dpdy = 0.5f * (pyp - pym);

    float sb = sqrtf(beta[b]);
    float fu = g_fa[(b << 20) + yx] * g_invnorm[b];
    float fv = g_fa[BHW + (b << 20) + yx] * g_invnorm[8 + b];

    g_unew[gid] = uc + DT * (-adv_u + NU * lap_u - dpdx) + sb * fu;
    g_vnew[gid] = vc + DT * (-adv_v + NU * lap_v - dpdy) + sb * fv;
}

// ------------------------- fwd FFT over x: one warp per packed row pair -------------------------
__global__ void __launch_bounds__(128) fft_fwd_div_kernel() {
    __shared__ float2 pool[4 * 1056];
    int tid = threadIdx.x, wid = tid >> 5, lane = tid & 31;
    int pairId = blockIdx.x * 4 + wid;       // b*512 + yp
    int b = pairId >> 9, yp = pairId & 511;
    int y0 = yp << 1, y1 = y0 + 1;
    int ub = b << 20;
    int r0 = y0 << 10, r1 = y1 << 10;
    int ym0 = ((y0 - 1) & 1023) << 10;
    int yp1 = ((y1 + 1) & 1023) << 10;

    float2 r[32];
    #pragma unroll
    for (int n1 = 0; n1 < 32; n1++) {
        int x = (n1 << 5) + lane;
        int xp = (x + 1) & 1023, xm = (x - 1) & 1023;
        float d0 = 0.5f * (g_unew[ub + r0 + xp] - g_unew[ub + r0 + xm])
                 + 0.5f * (g_vnew[ub + r1 + x]  - g_vnew[ub + ym0 + x]);
        float d1 = 0.5f * (g_unew[ub + r1 + xp] - g_unew[ub + r1 + xm])
                 + 0.5f * (g_vnew[ub + yp1 + x] - g_vnew[ub + r0 + x]);
        r[n1] = make_float2(d0, d1);
    }

    float2* zb = pool + wid * 1056;
    fft1024_warp(r, zb, lane);

    // write natural-order Z into zb, then untangle + compact store
    __syncwarp();
    #pragma unroll
    for (int k2 = 0; k2 < 32; k2++) zb[k2 * 33 + lane] = r[brev5(k2)];
    __syncwarp();

    float2* c0 = g_c1 + b * C1BATCH + y0 * C1ROW;
    float2* c1 = g_c1 + b * C1BATCH + y1 * C1ROW;
    #pragma unroll
    for (int m = 0; m < 17; m++) {
        int k = lane + (m << 5);
        if (k <= 512) {
            int km = (1024 - k) & 1023;
            float2 A = zb[(k >> 5) * 33 + (k & 31)];
            float2 B = zb[(km >> 5) * 33 + (km & 31)];
            c0[k] = make_float2(0.5f * (A.x + B.x), 0.5f * (A.y - B.y));
            c1[k] = make_float2(0.5f * (A.y + B.y), 0.5f * (B.x - A.x));
        }
    }
}

// ------------------------- fused column pipeline: one warp per compact column -------------------------
__global__ void __launch_bounds__(128) fft_col_poisson_kernel() {
    __shared__ float2 pool[4224];
    int tid = threadIdx.x, wid = tid >> 5, lane = tid & 31;
    int blk = blockIdx.x;                   // b*129 + g
    int b = blk / 129, g = blk - b * 129;
    int col0 = g << 2;
    float2* base = g_c1 + b * C1BATCH;

    // cooperative staged load: st[y*4 + c]
    int c = tid & 3, yy = tid >> 2;
    #pragma unroll
    for (int m = 0; m < 32; m++) {
        int y = (m << 5) + yy;
        pool[y * 4 + c] = base[y * C1ROW + col0 + c];
    }
    __syncthreads();

    float2 r[32];
    #pragma unroll
    for (int n1 = 0; n1 < 32; n1++)
        r[n1] = pool[(((n1 << 5) + lane) << 2) + wid];
    __syncthreads();

    float2* zb = pool + wid * 1056;
    fft1024_warp(r, zb, lane);

    int col = col0 + wid;                   // natural spectral kx (col <= 512 valid)
    float tkx = (float)min(col, 512);
    #pragma unroll
    for (int j = 0; j < 32; j++) {
        int ky = (brev5(j) << 5) + lane;
        int tky = min(ky, 1024 - ky);
        float k2v = tkx * tkx + (float)tky * (float)tky;
        float mm = (col == 0 && ky == 0) ? 0.0f
                 : (-1.0f / (39.47841760435743f * k2v)) * (1.0f / 1024.0f);
        r[j].x *= mm; r[j].y *= mm;
    }

    ifft1024_warp(r, zb, lane);

    __syncthreads();
    #pragma unroll
    for (int n1 = 0; n1 < 32; n1++)
        pool[(((n1 << 5) + lane) << 2) + wid] = r[n1];
    __syncthreads();
    #pragma unroll
    for (int m = 0; m < 32; m++) {
        int y = (m << 5) + yy;
        base[y * C1ROW + col0 + c] = pool[y * 4 + c];
    }
}

// ------------------------- inverse FFT over x: one warp per packed row pair -------------------------
__global__ void __launch_bounds__(128) fft_inv_real_kernel() {
    __shared__ float2 pool[4 * 1056];
    int tid = threadIdx.x, wid = tid >> 5, lane = tid & 31;
    int pairId = blockIdx.x * 4 + wid;
    int b = pairId >> 9, yp = pairId & 511;
    int y0 = yp << 1, y1 = y0 + 1;

    float2* zb = pool + wid * 1056;
    float2* c0s = zb;            // 513 slots
    float2* c1s = zb + 520;      // 513 slots (520+513 <= 1056)
    const float2* gc0 = g_c1 + b * C1BATCH + y0 * C1ROW;
    const float2* gc1 = g_c1 + b * C1BATCH + y1 * C1ROW;
    #pragma unroll
    for (int m = 0; m < 17; m++) {
        int k = lane + (m << 5);
        if (k <= 512) { c0s[k] = gc0[k]; c1s[k] = gc1[k]; }
    }
    __syncwarp();

    // pack B = S1 + i*S2 at positions r[j] = B[32*brev5(j) + lane]
    float2 r[32];
    #pragma unroll
    for (int j = 0; j < 32; j++) {
        int k = (brev5(j) << 5) + lane;
        float2 B;
        if (k <= 512) {
            float2 a = c0s[k], bb = c1s[k];
            B = make_float2(a.x - bb.y, a.y + bb.x);
        } else {
            int km = 1024 - k;
            float2 a = c0s[km], bb = c1s[km];
            B = make_float2(a.x + bb.y, -a.y + bb.x);
        }
        r[j] = B;
    }
    __syncwarp();

    ifft1024_warp(r, zb, lane);

    const float sc = 1.0f / 1024.0f;
    int bb2 = b << 20;
    #pragma unroll
    for (int n1 = 0; n1 < 32; n1++) {
        int x = (n1 << 5) + lane;
        g_pcorr[bb2 + (y0 << 10) + x] = r[n1].x * sc;
        g_pcorr[bb2 + (y1 << 10) + x] = r[n1].y * sc;
    }
}

// ------------------------- final: subtract grad(p_corr), stack output -------------------------
__global__ void final_kernel(const float* __restrict__ xin, float* __restrict__ out) {
    int gid = blockIdx.x * 256 + threadIdx.x;
    int b  = gid >> 20;
    int yx = gid & (HW - 1);
    int y = yx >> 10, x = yx & 1023;

    int ixp = (y << 10) | ((x + 1) & 1023);
    int ixm = (y << 10) | ((x - 1) & 1023);
    int iyp = (((y + 1) & 1023) << 10) | x;
    int iym = (((y - 1) & 1023) << 10) | x;

    int bb = b << 20;
    float pcc = g_pcorr[bb + yx];
    float pxp = g_pcorr[bb + ixp], pxm = g_pcorr[bb + ixm];
    float pyp = g_pcorr[bb + iyp], pym = g_pcorr[bb + iym];

    float uo = g_unew[gid] - 0.5f * (pxp - pxm);
    float vo = g_vnew[gid] - 0.5f * (pyp - pym);
    float po = xin[(size_t)(b * 3 + 2) * HW + yx] + pcc;

    out[(size_t)(b * 3 + 0) * HW + yx] = uo;
    out[(size_t)(b * 3 + 1) * HW + yx] = vo;
    out[(size_t)(b * 3 + 2) * HW + yx] = po;
}

// ------------------------- launch -------------------------
extern "C" void kernel_launch(void* const* d_in, const int* in_sizes, int n_in,
                              void* d_out, int out_size) {
    (void)in_sizes; (void)n_in; (void)out_size;
    const float* x    = (const float*)d_in[0];
    const float* beta = (const float*)d_in[1];
    const float* fu   = (const float*)d_in[2];
    const float* fv   = (const float*)d_in[3];
    float* out = (float*)d_out;

    smooth3_kernel<<<dim3(1024, 16), 256>>>(fu, fv);
    finalize_kernel<<<16, 256>>>();
    update_kernel<<<BHW / 256, 256>>>(x, beta);
    fft_fwd_div_kernel<<<1024, 128>>>();
    fft_col_poisson_kernel<<<NB * 129, 128>>>();
    fft_inv_real_kernel<<<1024, 128>>>();
    final_kernel<<<BHW / 256, 256>>>(x, out);
}

// round 8
// speedup vs baseline: 1.0098x; 1.0098x over previous
#include <cuda_runtime.h>
#include <math.h>

#define NB 8
#define NH 1024
#define NW 1024
#define HW (1 << 20)
#define BHW (NB * HW)

#define NU 0.01f
#define DT 0.01f

#define C1ROW 520                      // compact spectral row stride (slots 0..512 used, natural kx)
#define C1BATCH (1024 * C1ROW)

// ------------------------- device scratch -------------------------
__device__ float  g_fa[2 * BHW];
__device__ float  g_unew[BHW];
__device__ float  g_vnew[BHW];
__device__ float2 g_c1[NB * C1BATCH];
__device__ float  g_pcorr[BHW];
__device__ float  g_partials[16384];
__device__ float  g_invnorm[16];

// ------------------------- complex helpers -------------------------
__device__ __forceinline__ float2 cmul(float2 a, float2 b) {
    return make_float2(a.x * b.x - a.y * b.y, a.x * b.y + a.y * b.x);
}
__device__ __forceinline__ float2 cadd(float2 a, float2 b) { return make_float2(a.x + b.x, a.y + b.y); }
__device__ __forceinline__ float2 csub(float2 a, float2 b) { return make_float2(a.x - b.x, a.y - b.y); }

__device__ __forceinline__ constexpr int brev5(int v) {
    return ((v & 1) << 4) | ((v & 2) << 2) | (v & 4) | ((v & 8) >> 2) | ((v & 16) >> 4);
}

// W_32^q = exp(-2*pi*i*q/32), q=0..15
__constant__ float2 W32C[16] = {
    { 1.000000000f, -0.000000000f}, { 0.980785280f, -0.195090322f},
    { 0.923879533f, -0.382683432f}, { 0.831469612f, -0.555570233f},
    { 0.707106781f, -0.707106781f}, { 0.555570233f, -0.831469612f},
    { 0.382683432f, -0.923879533f}, { 0.195090322f, -0.980785280f},
    { 0.000000000f, -1.000000000f}, {-0.195090322f, -0.980785280f},
    {-0.382683432f, -0.923879533f}, {-0.555570233f, -0.831469612f},
    {-0.707106781f, -0.707106781f}, {-0.831469612f, -0.555570233f},
    {-0.923879533f, -0.382683432f}, {-0.980785280f, -0.195090322f},
};

// 32-pt in-place DIF (natural in, X[k] at r[brev5(k)])
__device__ __forceinline__ void dif32(float2* r) {
    #pragma unroll
    for (int t = 0; t < 5; t++) {
        const int h = 16 >> t;
        #pragma unroll
        for (int g = 0; g < (16 / h); g++) {
            #pragma unroll
            for (int q = 0; q < h; q++) {
                int i0 = ((g * h) << 1) + q, i1 = i0 + h;
                float2 A = r[i0], B = r[i1];
                r[i0] = cadd(A, B);
                r[i1] = cmul(csub(A, B), W32C[q << t]);
            }
        }
    }
}

// 32-pt in-place inverse DIT with conj twiddles (input r[j]=X[brev5(j)], natural out, unscaled)
__device__ __forceinline__ void dit32i(float2* r) {
    #pragma unroll
    for (int t = 0; t < 5; t++) {
        const int h = 1 << t;
        #pragma unroll
        for (int g = 0; g < (16 / h); g++) {
            #pragma unroll
            for (int q = 0; q < h; q++) {
                int i0 = ((g * h) << 1) + q, i1 = i0 + h;
                float2 A = r[i0], B = r[i1];
                float2 w = W32C[q << (4 - t)];
                w.y = -w.y;
                float2 tv = cmul(w, B);
                r[i0] = cadd(A, tv);
                r[i1] = csub(A, tv);
            }
        }
    }
}

// Warp 1024-pt forward FFT. In: r[n1] = z[32*n1 + lane]. Out: r[j] = Z[32*brev5(j) + lane].
__device__ __forceinline__ void fft1024_warp(float2* r, float2* zb, int lane) {
    dif32(r);
    float sn, cs;
    sincosf((float)lane * -6.135923151542565e-3f, &sn, &cs);   // -2*pi*lane/1024
    float2 w1 = make_float2(cs, sn), w = w1;
    #pragma unroll
    for (int k1 = 1; k1 < 32; k1++) {
        r[brev5(k1)] = cmul(r[brev5(k1)], w);
        w = cmul(w, w1);
    }
    __syncwarp();
    #pragma unroll
    for (int k1 = 0; k1 < 32; k1++) zb[lane * 33 + k1] = r[brev5(k1)];
    __syncwarp();
    #pragma unroll
    for (int n2 = 0; n2 < 32; n2++) r[n2] = zb[n2 * 33 + lane];
    dif32(r);
}

// Warp 1024-pt inverse FFT (unscaled). In: r[j] = X[32*brev5(j) + lane]. Out: r[n1] = x[32*n1 + lane].
__device__ __forceinline__ void ifft1024_warp(float2* r, float2* zb, int lane) {
    dit32i(r);
    float sn, cs;
    sincosf((float)lane * 6.135923151542565e-3f, &sn, &cs);    // +2*pi*lane/1024
    float2 w1 = make_float2(cs, sn), w = w1;
    #pragma unroll
    for (int n2 = 1; n2 < 32; n2++) {
        r[n2] = cmul(r[n2], w);
        w = cmul(w, w1);
    }
    __syncwarp();
    #pragma unroll
    for (int n2 = 0; n2 < 32; n2++) zb[lane * 33 + n2] = r[n2];
    __syncwarp();
    #pragma unroll
    for (int j = 0; j < 32; j++) r[j] = zb[brev5(j) * 33 + lane];
    dit32i(r);
}

// ------------------------- block reduce -------------------------
__device__ __forceinline__ float block_reduce_256(float v, float* red) {
    #pragma unroll
    for (int o = 16; o > 0; o >>= 1) v += __shfl_down_sync(0xffffffffu, v, o);
    int lane = threadIdx.x & 31, wid = threadIdx.x >> 5;
    if (lane == 0) red[wid] = v;
    __syncthreads();
    float s = 0.0f;
    if (wid == 0) {
        s = (lane < 8) ? red[lane] : 0.0f;
        #pragma unroll
        for (int o = 4; o > 0; o >>= 1) s += __shfl_down_sync(0xffffffffu, s, o);
    }
    return s;
}

// ------------------------- fused 3x smoothing + norm partials -------------------------
__global__ void smooth3_kernel(const float* __restrict__ su_ext,
                               const float* __restrict__ sv_ext) {
    __shared__ float t0[38][40];
    __shared__ float t1[38][40];
    __shared__ float red[8];
    int slab = blockIdx.y;
    int fb = slab >> 3, b = slab & 7;
    const float* src = (fb ? sv_ext : su_ext) + (b << 20);
    int tile = blockIdx.x;
    int ty0 = (tile >> 5) << 5;
    int tx0 = (tile & 31) << 5;
    int tid = threadIdx.x;

    for (int i = tid; i < 38 * 38; i += 256) {
        int ly = i / 38, lx = i - ly * 38;
        int gy = (ty0 + ly - 3) & 1023;
        int gx = (tx0 + lx - 3) & 1023;
        t0[ly][lx] = src[(gy << 10) + gx];
    }
    __syncthreads();
    for (int i = tid; i < 36 * 36; i += 256) {
        int ly = i / 36, lx = i - ly * 36;
        ly += 1; lx += 1;
        float c = t0[ly][lx];
        t1[ly][lx] = c + 0.1f * (t0[ly][lx-1] + t0[ly][lx+1] + t0[ly-1][lx] + t0[ly+1][lx] - 4.0f * c);
    }
    __syncthreads();
    for (int i = tid; i < 34 * 34; i += 256) {
        int ly = i / 34, lx = i - ly * 34;
        ly += 2; lx += 2;
        float c = t1[ly][lx];
        t0[ly][lx] = c + 0.1f * (t1[ly][lx-1] + t1[ly][lx+1] + t1[ly-1][lx] + t1[ly+1][lx] - 4.0f * c);
    }
    __syncthreads();
    float ss = 0.0f;
    float* dst = g_fa + fb * BHW + (b << 20);
    for (int i = tid; i < 1024; i += 256) {
        int ly = (i >> 5) + 3, lx = (i & 31) + 3;
        float c = t0[ly][lx];
        float o = c + 0.1f * (t0[ly][lx-1] + t0[ly][lx+1] + t0[ly-1][lx] + t0[ly+1][lx] - 4.0f * c);
        dst[((ty0 + ly - 3) << 10) + (tx0 + lx - 3)] = o;
        ss += o * o;
    }
    float tot = block_reduce_256(ss, red);
    if (tid == 0) g_partials[slab * 1024 + tile] = tot;
}

__global__ void finalize_kernel() {
    int r = blockIdx.x;
    float s = 0.0f;
    for (int i = threadIdx.x; i < 1024; i += 256) s += g_partials[r * 1024 + i];
    __shared__ float red[8];
    float tot = block_reduce_256(s, red);
    if (threadIdx.x == 0) {
        float nrm = sqrtf(tot);
        g_invnorm[r] = 1.0f / fmaxf(nrm, 1e-12f);
    }
}

// ------------------------- main update -------------------------
__global__ void update_kernel(const float* __restrict__ xin,
                              const float* __restrict__ beta) {
    int gid = blockIdx.x * 256 + threadIdx.x;
    int b  = gid >> 20;
    int yx = gid & (HW - 1);
    int y = yx >> 10, x = yx & 1023;

    const float* u = xin + (size_t)(b * 3 + 0) * HW;
    const float* v = xin + (size_t)(b * 3 + 1) * HW;
    const float* p = xin + (size_t)(b * 3 + 2) * HW;

    int ixp = (y << 10) | ((x + 1) & 1023);
    int ixm = (y << 10) | ((x - 1) & 1023);
    int iyp = (((y + 1) & 1023) << 10) | x;
    int iym = (((y - 1) & 1023) << 10) | x;

    float uc = u[yx], uxp = u[ixp], uxm = u[ixm], uyp = u[iyp], uym = u[iym];
    float vc = v[yx], vxp = v[ixp], vxm = v[ixm], vyp = v[iyp], vym = v[iym];
    float pxp = p[ixp], pxm = p[ixm], pyp = p[iyp], pym = p[iym];

    float adv_u = uc * 0.5f * (uxp - uxm) + vc * 0.5f * (uyp - uym);
    float adv_v = uc * 0.5f * (vxp - vxm) + vc * 0.5f * (vyp - vym);
    float lap_u = uxp + uxm + uyp + uym - 4.0f * uc;
    float lap_v = vxp + vxm + vyp + vym - 4.0f * vc;
    float dpdx = 0.5f * (pxp - pxm), dpdy = 0.5f * (pyp - pym);

    float sb = sqrtf(beta[b]);
    float fu = g_fa[(b << 20) + yx] * g_invnorm[b];
    float fv = g_fa[BHW + (b << 20) + yx] * g_invnorm[8 + b];

    g_unew[gid] = uc + DT * (-adv_u + NU * lap_u - dpdx) + sb * fu;
    g_vnew[gid] = vc + DT * (-adv_v + NU * lap_v - dpdy) + sb * fv;
}

// ------------------------- fwd FFT over x: one warp per packed row pair -------------------------
__global__ void __launch_bounds__(128) fft_fwd_div_kernel() {
    __shared__ float2 pool[4 * 1056];
    int tid = threadIdx.x, wid = tid >> 5, lane = tid & 31;
    int pairId = blockIdx.x * 4 + wid;       // b*512 + yp
    int b = pairId >> 9, yp = pairId & 511;
    int y0 = yp << 1, y1 = y0 + 1;
    int ub = b << 20;
    int r0 = y0 << 10, r1 = y1 << 10;
    int ym0 = ((y0 - 1) & 1023) << 10;
    int yp1 = ((y1 + 1) & 1023) << 10;

    float2 r[32];
    #pragma unroll
    for (int n1 = 0; n1 < 32; n1++) {
        int x = (n1 << 5) + lane;
        int xp = (x + 1) & 1023, xm = (x - 1) & 1023;
        float d0 = 0.5f * (g_unew[ub + r0 + xp] - g_unew[ub + r0 + xm])
                 + 0.5f * (g_vnew[ub + r1 + x]  - g_vnew[ub + ym0 + x]);
        float d1 = 0.5f * (g_unew[ub + r1 + xp] - g_unew[ub + r1 + xm])
                 + 0.5f * (g_vnew[ub + yp1 + x] - g_vnew[ub + r0 + x]);
        r[n1] = make_float2(d0, d1);
    }

    float2* zb = pool + wid * 1056;
    fft1024_warp(r, zb, lane);

    // write natural-order Z into zb, then untangle + compact store
    __syncwarp();
    #pragma unroll
    for (int k2 = 0; k2 < 32; k2++) zb[k2 * 33 + lane] = r[brev5(k2)];
    __syncwarp();

    float2* c0 = g_c1 + b * C1BATCH + y0 * C1ROW;
    float2* c1 = g_c1 + b * C1BATCH + y1 * C1ROW;
    #pragma unroll
    for (int m = 0; m < 17; m++) {
        int k = lane + (m << 5);
        if (k <= 512) {
            int km = (1024 - k) & 1023;
            float2 A = zb[(k >> 5) * 33 + (k & 31)];
            float2 B = zb[(km >> 5) * 33 + (km & 31)];
            c0[k] = make_float2(0.5f * (A.x + B.x), 0.5f * (A.y - B.y));
            c1[k] = make_float2(0.5f * (A.y + B.y), 0.5f * (B.x - A.x));
        }
    }
}

// ------------------------- fused column pipeline: one warp per compact column -------------------------
// Stage buffer: separate R/I float arrays, per-column stride 1032 floats (1032 % 32 == 8)
//  - stage write  (c = tid&3, y = m*32 + tid>>2): bank = (8c + y) % 32 -> all 32 banks once
//  - reg   gather (addr = wid*1032 + n1*32+lane): bank = (8*wid + lane) % 32 -> conflict-free
// Arena is time-shared with the per-warp FFT scratch (phases separated by __syncthreads).
__global__ void __launch_bounds__(128) fft_col_poisson_kernel() {
    __shared__ float2 arena[4224];           // 33.8 KB
    float* aR = (float*)arena;               // stageR: aR[c*1032 + y]   (4128 floats)
    float* aI = aR + 4224;                   // stageI: aI[c*1032 + y]   (4128 floats; total 8352 <= 8448)
    int tid = threadIdx.x, wid = tid >> 5, lane = tid & 31;
    int blk = blockIdx.x;                    // b*129 + g
    int b = blk / 129, g = blk - b * 129;
    int col0 = g << 2;
    float2* base = g_c1 + b * C1BATCH;

    int c = tid & 3, yy = tid >> 2;
    #pragma unroll
    for (int m = 0; m < 32; m++) {
        int y = (m << 5) + yy;
        float2 v = base[y * C1ROW + col0 + c];
        aR[c * 1032 + y] = v.x; aI[c * 1032 + y] = v.y;
    }
    __syncthreads();

    float2 r[32];
    #pragma unroll
    for (int n1 = 0; n1 < 32; n1++) {
        int idx = wid * 1032 + (n1 << 5) + lane;
        r[n1] = make_float2(aR[idx], aI[idx]);
    }
    __syncthreads();                         // stage fully consumed before zb overlays

    float2* zb = arena + wid * 1056;
    fft1024_warp(r, zb, lane);

    int col = col0 + wid;                    // natural spectral kx (col <= 512 valid)
    float tkx = (float)min(col, 512);
    #pragma unroll
    for (int j = 0; j < 32; j++) {
        int ky = (brev5(j) << 5) + lane;
        int tky = min(ky, 1024 - ky);
        float k2v = tkx * tkx + (float)tky * (float)tky;
        float mm = (col == 0 && ky == 0) ? 0.0f
                 : (-1.0f / (39.47841760435743f * k2v)) * (1.0f / 1024.0f);
        r[j].x *= mm; r[j].y *= mm;
    }

    ifft1024_warp(r, zb, lane);

    __syncthreads();                         // all zb use done before restaging
    #pragma unroll
    for (int n1 = 0; n1 < 32; n1++) {
        int idx = wid * 1032 + (n1 << 5) + lane;
        aR[idx] = r[n1].x; aI[idx] = r[n1].y;
    }
    __syncthreads();
    #pragma unroll
    for (int m = 0; m < 32; m++) {
        int y = (m << 5) + yy;
        base[y * C1ROW + col0 + c] = make_float2(aR[c * 1032 + y], aI[c * 1032 + y]);
    }
}

// ------------------------- inverse FFT over x: one warp per packed row pair -------------------------
__global__ void __launch_bounds__(128) fft_inv_real_kernel() {
    __shared__ float2 pool[4 * 1056];
    int tid = threadIdx.x, wid = tid >> 5, lane = tid & 31;
    int pairId = blockIdx.x * 4 + wid;
    int b = pairId >> 9, yp = pairId & 511;
    int y0 = yp << 1, y1 = y0 + 1;

    float2* zb = pool + wid * 1056;
    float2* c0s = zb;            // 513 slots
    float2* c1s = zb + 520;      // 513 slots (520+513 <= 1056)
    const float2* gc0 = g_c1 + b * C1BATCH + y0 * C1ROW;
    const float2* gc1 = g_c1 + b * C1BATCH + y1 * C1ROW;
    #pragma unroll
    for (int m = 0; m < 17; m++) {
        int k = lane + (m << 5);
        if (k <= 512) { c0s[k] = gc0[k]; c1s[k] = gc1[k]; }
    }
    __syncwarp();

    // pack B = S1 + i*S2 at positions r[j] = B[32*brev5(j) + lane]
    float2 r[32];
    #pragma unroll
    for (int j = 0; j < 32; j++) {
        int k = (brev5(j) << 5) + lane;
        float2 B;
        if (k <= 512) {
            float2 a = c0s[k], bb = c1s[k];
            B = make_float2(a.x - bb.y, a.y + bb.x);
        } else {
            int km = 1024 - k;
            float2 a = c0s[km], bb = c1s[km];
            B = make_float2(a.x + bb.y, -a.y + bb.x);
        }
        r[j] = B;
    }
    __syncwarp();

    ifft1024_warp(r, zb, lane);

    const float sc = 1.0f / 1024.0f;
    int bb2 = b << 20;
    #pragma unroll
    for (int n1 = 0; n1 < 32; n1++) {
        int x = (n1 << 5) + lane;
        g_pcorr[bb2 + (y0 << 10) + x] = r[n1].x * sc;
        g_pcorr[bb2 + (y1 << 10) + x] = r[n1].y * sc;
    }
}

// ------------------------- final: subtract grad(p_corr), stack output -------------------------
__global__ void final_kernel(const float* __restrict__ xin, float* __restrict__ out) {
    int gid = blockIdx.x * 256 + threadIdx.x;
    int b  = gid >> 20;
    int yx = gid & (HW - 1);
    int y = yx >> 10, x = yx & 1023;

    int ixp = (y << 10) | ((x + 1) & 1023);
    int ixm = (y << 10) | ((x - 1) & 1023);
    int iyp = (((y + 1) & 1023) << 10) | x;
    int iym = (((y - 1) & 1023) << 10) | x;

    int bb = b << 20;
    float pcc = g_pcorr[bb + yx];
    float pxp = g_pcorr[bb + ixp], pxm = g_pcorr[bb + ixm];
    float pyp = g_pcorr[bb + iyp], pym = g_pcorr[bb + iym];

    float uo = g_unew[gid] - 0.5f * (pxp - pxm);
    float vo = g_vnew[gid] - 0.5f * (pyp - pym);
    float po = xin[(size_t)(b * 3 + 2) * HW + yx] + pcc;

    out[(size_t)(b * 3 + 0) * HW + yx] = uo;
    out[(size_t)(b * 3 + 1) * HW + yx] = vo;
    out[(size_t)(b * 3 + 2) * HW + yx] = po;
}

// ------------------------- launch -------------------------
extern "C" void kernel_launch(void* const* d_in, const int* in_sizes, int n_in,
                              void* d_out, int out_size) {
    (void)in_sizes; (void)n_in; (void)out_size;
    const float* x    = (const float*)d_in[0];
    const float* beta = (const float*)d_in[1];
    const float* fu   = (const float*)d_in[2];
    const float* fv   = (const float*)d_in[3];
    float* out = (float*)d_out;

    smooth3_kernel<<<dim3(1024, 16), 256>>>(fu, fv);
    finalize_kernel<<<16, 256>>>();
    update_kernel<<<BHW / 256, 256>>>(x, beta);
    fft_fwd_div_kernel<<<1024, 128>>>();
    fft_col_poisson_kernel<<<NB * 129, 128>>>();
    fft_inv_real_kernel<<<1024, 128>>>();
    final_kernel<<<BHW / 256, 256>>>(x, out);
}